// round 9
// baseline (speedup 1.0000x reference)
#include <cuda_runtime.h>
#include <cuda_bf16.h>
#include <stdint.h>

// GatherRouter combine: out[tag[i]] += data[i], 65536 rows x 1024 fp32 -> 16384 slots.
// k_bucket: fixed-capacity bucketing (Poisson(4)/slot; CAP=32 => overflow ~1e-19),
//           int4-vectorized tag loads, 4 independent atomics per thread.
// k_reduce: one slot/block. Metadata (cursor + rows[0..8)) fetched as three parallel
//           loads, then EIGHT unconditional LDG.128 per thread. Lanes beyond cnt
//           pointer-select to g_zero (L1-resident 4KB of zeros) => branchless adds,
//           no serial tail for 97.9% of slots (P[cnt<=8], Poisson mean 4).

#define NROWS   65536          // pow2
#define DDIM    1024
#define NSLOTS  16384
#define CAP     32             // one 128B line per bucket

__device__ int   g_cursor[NSLOTS];      // zeroed at load; reset by k_reduce each launch
__device__ int   g_rows[NSLOTS * CAP];  // 2 MB scratch (stale entries masked by cnt)
__device__ float g_zero[DDIM];          // never written: permanent zeros, L1-hot

// ---------------------------------------------------------------------------
__global__ void k_bucket(const int* __restrict__ tags) {
    int i = blockIdx.x * blockDim.x + threadIdx.x;          // 16384 threads
    int4 tv = __ldg((const int4*)tags + i);
    int base = i * 4;
    int t0 = tv.x & (NSLOTS - 1);
    int t1 = tv.y & (NSLOTS - 1);
    int t2 = tv.z & (NSLOTS - 1);
    int t3 = tv.w & (NSLOTS - 1);
    int p0 = atomicAdd(&g_cursor[t0], 1);
    int p1 = atomicAdd(&g_cursor[t1], 1);
    int p2 = atomicAdd(&g_cursor[t2], 1);
    int p3 = atomicAdd(&g_cursor[t3], 1);
    if (p0 < CAP) g_rows[t0 * CAP + p0] = base + 0;
    if (p1 < CAP) g_rows[t1 * CAP + p1] = base + 1;
    if (p2 < CAP) g_rows[t2 * CAP + p2] = base + 2;
    if (p3 < CAP) g_rows[t3 * CAP + p3] = base + 3;
}

// ---------------------------------------------------------------------------
__global__ __launch_bounds__(256) void k_reduce(const float* __restrict__ in,
                                                float* __restrict__ out) {
    const int slot = blockIdx.x;
    const int t    = threadIdx.x;

    // ---- metadata: three independent loads, one round trip ----
    int  cnt = g_cursor[slot];
    int4 iv0 = __ldg((const int4*)&g_rows[slot * CAP]);      // rows[0..3]
    int4 iv1 = __ldg((const int4*)&g_rows[slot * CAP + 4]);  // rows[4..7]
    cnt = (cnt > CAP) ? CAP : cnt;

    // ---- branchless base pointers: invalid lanes read the zero row ----
    const float* zp = g_zero;
    const float* b0 = (cnt > 0) ? in + (size_t)(iv0.x & (NROWS - 1)) * DDIM : zp;
    const float* b1 = (cnt > 1) ? in + (size_t)(iv0.y & (NROWS - 1)) * DDIM : zp;
    const float* b2 = (cnt > 2) ? in + (size_t)(iv0.z & (NROWS - 1)) * DDIM : zp;
    const float* b3 = (cnt > 3) ? in + (size_t)(iv0.w & (NROWS - 1)) * DDIM : zp;
    const float* b4 = (cnt > 4) ? in + (size_t)(iv1.x & (NROWS - 1)) * DDIM : zp;
    const float* b5 = (cnt > 5) ? in + (size_t)(iv1.y & (NROWS - 1)) * DDIM : zp;
    const float* b6 = (cnt > 6) ? in + (size_t)(iv1.z & (NROWS - 1)) * DDIM : zp;
    const float* b7 = (cnt > 7) ? in + (size_t)(iv1.w & (NROWS - 1)) * DDIM : zp;

    // ---- 8 data loads in flight, back-to-back ----
    float4 v0 = __ldg((const float4*)b0 + t);
    float4 v1 = __ldg((const float4*)b1 + t);
    float4 v2 = __ldg((const float4*)b2 + t);
    float4 v3 = __ldg((const float4*)b3 + t);
    float4 v4 = __ldg((const float4*)b4 + t);
    float4 v5 = __ldg((const float4*)b5 + t);
    float4 v6 = __ldg((const float4*)b6 + t);
    float4 v7 = __ldg((const float4*)b7 + t);

    float4 acc;
    acc.x = ((v0.x + v1.x) + (v2.x + v3.x)) + ((v4.x + v5.x) + (v6.x + v7.x));
    acc.y = ((v0.y + v1.y) + (v2.y + v3.y)) + ((v4.y + v5.y) + (v6.y + v7.y));
    acc.z = ((v0.z + v1.z) + (v2.z + v3.z)) + ((v4.z + v5.z) + (v6.z + v7.z));
    acc.w = ((v0.w + v1.w) + (v2.w + v3.w)) + ((v4.w + v5.w) + (v6.w + v7.w));

    // ---- rare tail (cnt > 8): 2.1% of slots ----
    for (int r = 8; r < cnt; r++) {
        int row = g_rows[slot * CAP + r] & (NROWS - 1);
        float4 v = __ldg((const float4*)(in + (size_t)row * DDIM) + t);
        acc.x += v.x; acc.y += v.y; acc.z += v.z; acc.w += v.w;
    }

    // streaming store: output is written once, never re-read
    __stcs((float4*)(out + (size_t)slot * DDIM) + t, acc);

    // reset cursor for next graph replay (off the critical path)
    __syncthreads();
    if (t == 0) g_cursor[slot] = 0;
}

// ---------------------------------------------------------------------------
extern "C" void kernel_launch(void* const* d_in, const int* in_sizes, int n_in,
                              void* d_out, int out_size) {
    const float* data = (const float*)d_in[0];
    const int*   tags = (const int*)d_in[1];
    float*       out  = (float*)d_out;

    k_bucket<<<128, 128>>>(tags);          // 16384 threads x 4 tags
    k_reduce<<<NSLOTS, 256>>>(data, out);
}

// round 10
// speedup vs baseline: 1.0380x; 1.0380x over previous
#include <cuda_runtime.h>
#include <cuda_bf16.h>
#include <stdint.h>

// GatherRouter combine: out[tag[i]] += data[i], 65536 rows x 1024 fp32 -> 16384 slots.
// k_bucket: int4-vectorized tags, 4 independent atomics/thread, uint16 row indices
//           (NROWS=65536 fits 16 bits; halves metadata traffic).
// k_reduce: 2 slots/block. Metadata = one int2 (both cursors) + two 8B loads
//           (first 4 uint16 indices per slot), then 8 unconditional LDG.128
//           (masked lanes -> row 0, L1-hot, weight-0 FFMA). Pairwise tail.

#define NROWS   65536
#define DDIM    1024
#define NSLOTS  16384
#define CAP     32              // 32 x 2B = 64B per bucket

__device__ int            g_cursor[NSLOTS];                  // zeroed at load; reset each launch
__device__ unsigned short g_rows[NSLOTS * CAP];              // 1 MB scratch

// ---------------------------------------------------------------------------
__global__ void k_bucket(const int* __restrict__ tags) {
    int i = blockIdx.x * blockDim.x + threadIdx.x;           // 16384 threads
    int4 tv = __ldg((const int4*)tags + i);
    int base = i * 4;
    int t0 = tv.x & (NSLOTS - 1);
    int t1 = tv.y & (NSLOTS - 1);
    int t2 = tv.z & (NSLOTS - 1);
    int t3 = tv.w & (NSLOTS - 1);
    int p0 = atomicAdd(&g_cursor[t0], 1);
    int p1 = atomicAdd(&g_cursor[t1], 1);
    int p2 = atomicAdd(&g_cursor[t2], 1);
    int p3 = atomicAdd(&g_cursor[t3], 1);
    if (p0 < CAP) g_rows[t0 * CAP + p0] = (unsigned short)(base + 0);
    if (p1 < CAP) g_rows[t1 * CAP + p1] = (unsigned short)(base + 1);
    if (p2 < CAP) g_rows[t2 * CAP + p2] = (unsigned short)(base + 2);
    if (p3 < CAP) g_rows[t3 * CAP + p3] = (unsigned short)(base + 3);
}

// ---------------------------------------------------------------------------
__device__ __forceinline__ float4 row_ld(const float* in, unsigned row, int t) {
    return __ldg((const float4*)(in + (size_t)row * DDIM) + t);
}

__global__ __launch_bounds__(256) void k_reduce(const float* __restrict__ in,
                                                float* __restrict__ out) {
    const int s0 = blockIdx.x * 2;
    const int s1 = s0 + 1;
    const int t  = threadIdx.x;

    // ---- metadata: three parallel loads (int2 cursors + 2x 8B index vectors) ----
    int2 cp = *(const int2*)&g_cursor[s0];
    // first 4 uint16 indices of each bucket, as two 32-bit words each
    uint2 ia = __ldg((const uint2*)&g_rows[s0 * CAP]);
    uint2 ib = __ldg((const uint2*)&g_rows[s1 * CAP]);
    int cnt0 = (cp.x > CAP) ? CAP : cp.x;
    int cnt1 = (cp.y > CAP) ? CAP : cp.y;

    unsigned a0 = ia.x & 0xFFFFu, a1 = ia.x >> 16;
    unsigned a2 = ia.y & 0xFFFFu, a3 = ia.y >> 16;
    unsigned b0 = ib.x & 0xFFFFu, b1 = ib.x >> 16;
    unsigned b2 = ib.y & 0xFFFFu, b3 = ib.y >> 16;

    // masked lanes -> row 0 (L1-hot after first touch), weight 0
    if (cnt0 <= 0) a0 = 0;  if (cnt0 <= 1) a1 = 0;
    if (cnt0 <= 2) a2 = 0;  if (cnt0 <= 3) a3 = 0;
    if (cnt1 <= 0) b0 = 0;  if (cnt1 <= 1) b1 = 0;
    if (cnt1 <= 2) b2 = 0;  if (cnt1 <= 3) b3 = 0;
    float wa0 = (cnt0 > 0) ? 1.f : 0.f, wa1 = (cnt0 > 1) ? 1.f : 0.f;
    float wa2 = (cnt0 > 2) ? 1.f : 0.f, wa3 = (cnt0 > 3) ? 1.f : 0.f;
    float wb0 = (cnt1 > 0) ? 1.f : 0.f, wb1 = (cnt1 > 1) ? 1.f : 0.f;
    float wb2 = (cnt1 > 2) ? 1.f : 0.f, wb3 = (cnt1 > 3) ? 1.f : 0.f;

    // ---- 8 data loads in flight ----
    float4 va0 = row_ld(in, a0, t);
    float4 va1 = row_ld(in, a1, t);
    float4 va2 = row_ld(in, a2, t);
    float4 va3 = row_ld(in, a3, t);
    float4 vb0 = row_ld(in, b0, t);
    float4 vb1 = row_ld(in, b1, t);
    float4 vb2 = row_ld(in, b2, t);
    float4 vb3 = row_ld(in, b3, t);

    float4 acc0, acc1;
    acc0.x = fmaf(wa0, va0.x, fmaf(wa1, va1.x, fmaf(wa2, va2.x, wa3 * va3.x)));
    acc0.y = fmaf(wa0, va0.y, fmaf(wa1, va1.y, fmaf(wa2, va2.y, wa3 * va3.y)));
    acc0.z = fmaf(wa0, va0.z, fmaf(wa1, va1.z, fmaf(wa2, va2.z, wa3 * va3.z)));
    acc0.w = fmaf(wa0, va0.w, fmaf(wa1, va1.w, fmaf(wa2, va2.w, wa3 * va3.w)));
    acc1.x = fmaf(wb0, vb0.x, fmaf(wb1, vb1.x, fmaf(wb2, vb2.x, wb3 * vb3.x)));
    acc1.y = fmaf(wb0, vb0.y, fmaf(wb1, vb1.y, fmaf(wb2, vb2.y, wb3 * vb3.y)));
    acc1.z = fmaf(wb0, vb0.z, fmaf(wb1, vb1.z, fmaf(wb2, vb2.z, wb3 * vb3.z)));
    acc1.w = fmaf(wb0, vb0.w, fmaf(wb1, vb1.w, fmaf(wb2, vb2.w, wb3 * vb3.w)));

    // ---- tails (cnt > 4): ~0.8 rows/slot expected, independent pairs ----
    for (int r = 4; r < cnt0; r++) {
        unsigned ra = g_rows[s0 * CAP + r];
        float4 v = row_ld(in, ra, t);
        acc0.x += v.x; acc0.y += v.y; acc0.z += v.z; acc0.w += v.w;
    }
    for (int r = 4; r < cnt1; r++) {
        unsigned rb = g_rows[s1 * CAP + r];
        float4 v = row_ld(in, rb, t);
        acc1.x += v.x; acc1.y += v.y; acc1.z += v.z; acc1.w += v.w;
    }

    __stcs((float4*)(out + (size_t)s0 * DDIM) + t, acc0);
    __stcs((float4*)(out + (size_t)s1 * DDIM) + t, acc1);

    // reset cursors for next graph replay
    __syncthreads();
    if (t < 2) g_cursor[s0 + t] = 0;
}

// ---------------------------------------------------------------------------
extern "C" void kernel_launch(void* const* d_in, const int* in_sizes, int n_in,
                              void* d_out, int out_size) {
    const float* data = (const float*)d_in[0];
    const int*   tags = (const int*)d_in[1];
    float*       out  = (float*)d_out;

    k_bucket<<<128, 128>>>(tags);            // 16384 threads x 4 tags
    k_reduce<<<NSLOTS / 2, 256>>>(data, out);
}